// round 14
// baseline (speedup 1.0000x reference)
#include <cuda_runtime.h>
#include <cuda_fp16.h>
#include <cstdint>
#include <math.h>

#define NB 2
#define NH 16
#define SEQ 2048
#define DH 128
#define DM 2048          // NH*DH
#define MTOK (NB*SEQ)    // 4096

// Scratch (static device allocations — allowed; no cudaMalloc anywhere)
__device__ __half g_qkv[(size_t)3 * NB * NH * SEQ * DH];  // [3][B][H][S][D] fp16
__device__ __half g_xh[(size_t)MTOK * DM];      // x fp16            [M][K]
__device__ __half g_wqkvh[(size_t)3 * DM * DM]; // W_qkv^T fp16      [N=6144][K]
__device__ __half g_wouth[(size_t)DM * DM];     // W_out^T fp16      [N=2048][K]
__device__ __half g_ctxh[(size_t)MTOK * DM];    // ctx fp16          [M][K]

// ---------------------------------------------------------------------------
// helpers
// ---------------------------------------------------------------------------
__device__ __forceinline__ void mma_f16(float& c0, float& c1, float& c2,
                                        float& c3, unsigned a0, unsigned a1,
                                        unsigned a2, unsigned a3, unsigned b0,
                                        unsigned b1) {
  asm volatile(
      "mma.sync.aligned.m16n8k16.row.col.f32.f16.f16.f32 "
      "{%0,%1,%2,%3},{%4,%5,%6,%7},{%8,%9},{%0,%1,%2,%3};\n"
      : "+f"(c0), "+f"(c1), "+f"(c2), "+f"(c3)
      : "r"(a0), "r"(a1), "r"(a2), "r"(a3), "r"(b0), "r"(b1));
}
__device__ __forceinline__ unsigned smem_u32(const void* p) {
  return (unsigned)__cvta_generic_to_shared(p);
}
#define CP16(dst_u32, gptr) \
  asm volatile("cp.async.cg.shared.global [%0], [%1], 16;\n" ::"r"(dst_u32), \
               "l"(gptr))
#define LDMATRIX_X4(v0, v1, v2, v3, addr)                               \
  asm volatile(                                                         \
      "ldmatrix.sync.aligned.m8n8.x4.shared.b16 {%0,%1,%2,%3}, [%4];"   \
      : "=r"(v0), "=r"(v1), "=r"(v2), "=r"(v3)                          \
      : "r"(addr))
#define LDMATRIX_X4_TRANS(v0, v1, v2, v3, addr)                        \
  asm volatile(                                                        \
      "ldmatrix.sync.aligned.m8n8.x4.trans.shared.b16 {%0,%1,%2,%3}, " \
      "[%4];"                                                          \
      : "=r"(v0), "=r"(v1), "=r"(v2), "=r"(v3)                         \
      : "r"(addr))

__device__ __forceinline__ unsigned pack_h2(float a, float b) {
  __half2 h = __floats2half2_rn(a, b);
  return *(unsigned*)&h;
}

// ---------------------------------------------------------------------------
// Prepass 1: x (fp32) -> g_xh (fp16), layout unchanged
// ---------------------------------------------------------------------------
__global__ void x_to_h_kernel(const float4* __restrict__ src, int n4) {
  __half2* dst = (__half2*)g_xh;
  for (int i = blockIdx.x * blockDim.x + threadIdx.x; i < n4;
       i += gridDim.x * blockDim.x) {
    float4 v = src[i];
    dst[2 * i] = __floats2half2_rn(v.x, v.y);
    dst[2 * i + 1] = __floats2half2_rn(v.z, v.w);
  }
}

// ---------------------------------------------------------------------------
// Prepass 2: W [K=2048][NCOLS] fp32 -> W^T [NCOLS][2048] fp16
// ---------------------------------------------------------------------------
template <int NCOLS, int WHICH>
__global__ void transpose_h_kernel(const float* __restrict__ src) {
  __half* dst = (WHICH == 1) ? g_wqkvh : g_wouth;
  __shared__ float tile[32][33];
  const int n0 = blockIdx.x * 32, k0 = blockIdx.y * 32;
  const int tx = threadIdx.x, ty = threadIdx.y;  // 32 x 8
#pragma unroll
  for (int i = 0; i < 32; i += 8)
    tile[ty + i][tx] = src[(size_t)(k0 + ty + i) * NCOLS + n0 + tx];
  __syncthreads();
#pragma unroll
  for (int i = 0; i < 32; i += 8)
    dst[(size_t)(n0 + ty + i) * DM + k0 + tx] =
        __float2half_rn(tile[tx][ty + i]);
}

// ---------------------------------------------------------------------------
// FP16 tensor-core GEMM: C[M,N] = A[M,2048](h) @ B^T (B stored [N][2048](h))
// CTA 128x256, K-tile 64, 8 warps (2m x 4n), warp tile 64x64, mma m16n8k16.
// Fragments via ldmatrix.x4 (8 LDSM + 32 HMMA per warp per k16-step).
// Row stride 72 halves = 36 words (==4 mod 32): every 8x16B matrix fetch
// covers all 32 banks exactly once -> conflict-free.
// Double-buffered cp.async; 110592 B smem; 1 CTA/SM.
// ---------------------------------------------------------------------------
#define SH 72                     // halves per smem row
#define A_TILE_H (128 * SH)
#define B_TILE_H (256 * SH)
#define GEMM_SMEM ((2 * A_TILE_H + 2 * B_TILE_H) * 2)  // 110592 B

template <int N, bool QKV_SCATTER, bool A_FROM_CTX>
__global__ __launch_bounds__(256, 1) void gemm_h_kernel(
    const float* __restrict__ bias, float* __restrict__ Cout) {
  extern __shared__ __half smh[];
  const __half* A = A_FROM_CTX ? g_ctxh : g_xh;
  const __half* Bw = QKV_SCATTER ? g_wqkvh : g_wouth;
  __half* AsBase = smh;                  // [2][128][72]
  __half* BsBase = smh + 2 * A_TILE_H;   // [2][256][72]
  const int K = DM;
  const int bm = blockIdx.y * 128, bn = blockIdx.x * 256;
  const int tid = threadIdx.x;
  const int warp = tid >> 5, lane = tid & 31;
  const int wm = (warp & 1) * 64;   // warp m offset
  const int wn = (warp >> 1) * 64;  // warp n offset

  float acc[4][8][4];
#pragma unroll
  for (int mf = 0; mf < 4; mf++)
#pragma unroll
    for (int nf = 0; nf < 8; nf++)
#pragma unroll
      for (int i = 0; i < 4; i++) acc[mf][nf][i] = 0.f;

  auto load_tile = [&](int k0, int buf) {
    __half* as = AsBase + buf * A_TILE_H;
    __half* bs = BsBase + buf * B_TILE_H;
    // A: 128 rows x 8 chunks = 1024 -> 4/thread
#pragma unroll
    for (int i = 0; i < 4; i++) {
      int cid = tid + i * 256;
      int row = cid >> 3, u = cid & 7;
      CP16(smem_u32(as + row * SH + u * 8),
           A + (size_t)(bm + row) * K + k0 + u * 8);
    }
    // B: 256 rows x 8 chunks = 2048 -> 8/thread
#pragma unroll
    for (int i = 0; i < 8; i++) {
      int cid = tid + i * 256;
      int row = cid >> 3, u = cid & 7;
      CP16(smem_u32(bs + row * SH + u * 8),
           Bw + (size_t)(bn + row) * K + k0 + u * 8);
    }
    asm volatile("cp.async.commit_group;\n");
  };

  load_tile(0, 0);

  const int lr = lane >> 2, lc = lane & 3;
  // ldmatrix lane addressing: lanes 0-15 -> rows, lanes 16-31 -> k+8 column
  const int lrow = lane & 15, lkh = (lane >> 4) * 8;

  for (int t = 0; t < K / 64; t++) {
    if (t + 1 < K / 64) {
      load_tile((t + 1) * 64, (t + 1) & 1);
      asm volatile("cp.async.wait_group 1;\n");
    } else {
      asm volatile("cp.async.wait_group 0;\n");
    }
    __syncthreads();

    const __half* as = AsBase + (t & 1) * A_TILE_H;
    const __half* bs = BsBase + (t & 1) * B_TILE_H;

#pragma unroll
    for (int ks = 0; ks < 4; ks++) {
      const int kh = ks * 16;
      // A frags: 4 ldmatrix.x4 -> a[mf][0..3]
      unsigned a[4][4];
#pragma unroll
      for (int mf = 0; mf < 4; mf++) {
        unsigned addr =
            smem_u32(as + (wm + mf * 16 + lrow) * SH + kh + lkh);
        LDMATRIX_X4(a[mf][0], a[mf][1], a[mf][2], a[mf][3], addr);
      }
      // B frags: 4 ldmatrix.x4; pair p covers n-groups 2p (r0,r2), 2p+1 (r1,r3)
      unsigned b[4][4];
#pragma unroll
      for (int p = 0; p < 4; p++) {
        unsigned addr =
            smem_u32(bs + (wn + p * 16 + lrow) * SH + kh + lkh);
        LDMATRIX_X4(b[p][0], b[p][1], b[p][2], b[p][3], addr);
      }
#pragma unroll
      for (int mf = 0; mf < 4; mf++)
#pragma unroll
        for (int p = 0; p < 4; p++) {
          mma_f16(acc[mf][2 * p][0], acc[mf][2 * p][1], acc[mf][2 * p][2],
                  acc[mf][2 * p][3], a[mf][0], a[mf][1], a[mf][2], a[mf][3],
                  b[p][0], b[p][2]);
          mma_f16(acc[mf][2 * p + 1][0], acc[mf][2 * p + 1][1],
                  acc[mf][2 * p + 1][2], acc[mf][2 * p + 1][3], a[mf][0],
                  a[mf][1], a[mf][2], a[mf][3], b[p][1], b[p][3]);
        }
    }
    __syncthreads();
  }

  // Epilogue
#pragma unroll
  for (int mf = 0; mf < 4; mf++) {
#pragma unroll
    for (int nf = 0; nf < 8; nf++) {
      int r0 = bm + wm + mf * 16 + lr;
      int c0 = bn + wn + nf * 8 + 2 * lc;
      float bia0 = bias[c0], bia1 = bias[c0 + 1];
      float v00 = acc[mf][nf][0] + bia0, v01 = acc[mf][nf][1] + bia1;
      float v10 = acc[mf][nf][2] + bia0, v11 = acc[mf][nf][3] + bia1;
      if (QKV_SCATTER) {
        int which = c0 >> 11, rr = c0 & 2047;
        int h = rr >> 7, d = rr & 127;
#pragma unroll
        for (int rv = 0; rv < 2; rv++) {
          int m = r0 + rv * 8;
          int b = m >> 11, sidx = m & 2047;
          __half* dst = g_qkv +
                        (size_t)(((which * NB + b) * NH + h) * SEQ + sidx) *
                            DH +
                        d;
          *(__half2*)dst = rv ? __floats2half2_rn(v10, v11)
                              : __floats2half2_rn(v00, v01);
        }
      } else {
        *(float2*)(Cout + (size_t)r0 * N + c0) = make_float2(v00, v01);
        *(float2*)(Cout + (size_t)(r0 + 8) * N + c0) = make_float2(v10, v11);
      }
    }
  }
}

// ---------------------------------------------------------------------------
// FP16 flash attention (unchanged from R13 — passing).
// ---------------------------------------------------------------------------
#define FQ_S 136
#define FK_S 136
#define FV_S 136
#define FLASH_SMEM ((128 * FQ_S + 64 * FK_S + 64 * FV_S) * 2)  // 69632 B

__global__ __launch_bounds__(256, 2) void flash_h_kernel() {
  extern __shared__ __half smh[];
  __half* Qs = smh;                    // [128][136]
  __half* Ks = Qs + 128 * FQ_S;        // [64][136]
  __half* Vs = Ks + 64 * FK_S;         // [64][136]

  const int bh = blockIdx.y;
  const int qt = gridDim.x - 1 - blockIdx.x;  // longest CTAs first
  const int q0 = qt * 128;
  const __half* Qg = g_qkv + (size_t)bh * SEQ * DH + (size_t)q0 * DH;
  const __half* Kg = g_qkv + (size_t)(32 + bh) * SEQ * DH;
  const __half* Vg = g_qkv + (size_t)(64 + bh) * SEQ * DH;
  const int tid = threadIdx.x;
  const int warp = tid >> 5, lane = tid & 31;
  const int lr = lane >> 2, lc = lane & 3;
  const int wm = warp * 16;

#pragma unroll
  for (int u = 0; u < 8; u++) {
    int cid = tid + u * 256;
    int r = cid >> 4, c = (cid & 15) * 8;
    CP16(smem_u32(Qs + r * FQ_S + c), Qg + (size_t)r * DH + c);
  }
  asm volatile("cp.async.commit_group;\n");

  const int lsel = lane >> 3, lrow8 = lane & 7;
  const unsigned ldm_off =
      (unsigned)((lrow8 + 8 * (lsel & 1)) * FV_S + 8 * (lsel >> 1));

  float o[16][4];
#pragma unroll
  for (int nf = 0; nf < 16; nf++)
#pragma unroll
    for (int i = 0; i < 4; i++) o[nf][i] = 0.f;
  float m0 = -1e30f, m1 = -1e30f, l0 = 0.f, l1 = 0.f;

  const float scale = 0.08838834764831845f;  // 1/sqrt(128)
  const int nkt = 2 * qt + 2;

  for (int kt = 0; kt < nkt; kt++) {
    const int k0 = kt * 64;
    __syncthreads();
#pragma unroll
    for (int u = 0; u < 4; u++) {
      int cid = tid + u * 256;
      int r = cid >> 4, c = (cid & 15) * 8;
      CP16(smem_u32(Ks + r * FK_S + c), Kg + (size_t)(k0 + r) * DH + c);
      CP16(smem_u32(Vs + r * FV_S + c), Vg + (size_t)(k0 + r) * DH + c);
    }
    asm volatile("cp.async.commit_group;\ncp.async.wait_group 0;\n");
    __syncthreads();

    float sc[8][4];
#pragma unroll
    for (int nf = 0; nf < 8; nf++)
#pragma unroll
      for (int i = 0; i < 4; i++) sc[nf][i] = 0.f;
#pragma unroll
    for (int ks = 0; ks < 8; ks++) {
      const int kh = ks * 16;
      const __half* ap = Qs + (wm + lr) * FQ_S + kh + 2 * lc;
      unsigned a0 = *(const unsigned*)(ap);
      unsigned a1 = *(const unsigned*)(ap + 8 * FQ_S);
      unsigned a2 = *(const unsigned*)(ap + 8);
      unsigned a3 = *(const unsigned*)(ap + 8 * FQ_S + 8);
#pragma unroll
      for (int nf = 0; nf < 8; nf++) {
        const __half* bp = Ks + (nf * 8 + lr) * FK_S + kh + 2 * lc;
        unsigned b0 = *(const unsigned*)(bp);
        unsigned b1 = *(const unsigned*)(bp + 8);
        mma_f16(sc[nf][0], sc[nf][1], sc[nf][2], sc[nf][3], a0, a1, a2, a3,
                b0, b1);
      }
    }
#pragma unroll
    for (int nf = 0; nf < 8; nf++)
#pragma unroll
      for (int i = 0; i < 4; i++) sc[nf][i] *= scale;

    const int r0g = q0 + wm + lr, r1g = r0g + 8;
    if (k0 + 63 > r0g) {
#pragma unroll
      for (int nf = 0; nf < 8; nf++) {
        int cg = k0 + nf * 8 + 2 * lc;
        if (cg > r0g) sc[nf][0] = -1e30f;
        if (cg + 1 > r0g) sc[nf][1] = -1e30f;
        if (cg > r1g) sc[nf][2] = -1e30f;
        if (cg + 1 > r1g) sc[nf][3] = -1e30f;
      }
    }

    float mx0 = sc[0][0], mx1 = sc[0][2];
#pragma unroll
    for (int nf = 0; nf < 8; nf++) {
      mx0 = fmaxf(mx0, fmaxf(sc[nf][0], sc[nf][1]));
      mx1 = fmaxf(mx1, fmaxf(sc[nf][2], sc[nf][3]));
    }
    mx0 = fmaxf(mx0, __shfl_xor_sync(0xffffffffu, mx0, 1));
    mx0 = fmaxf(mx0, __shfl_xor_sync(0xffffffffu, mx0, 2));
    mx1 = fmaxf(mx1, __shfl_xor_sync(0xffffffffu, mx1, 1));
    mx1 = fmaxf(mx1, __shfl_xor_sync(0xffffffffu, mx1, 2));
    float mn0 = fmaxf(m0, mx0), mn1 = fmaxf(m1, mx1);
    float cr0 = __expf(m0 - mn0), cr1 = __expf(m1 - mn1);
    m0 = mn0; m1 = mn1;
    float rs0 = 0.f, rs1 = 0.f;
    unsigned ph[8][2];
#pragma unroll
    for (int nf = 0; nf < 8; nf++) {
      float p00 = __expf(sc[nf][0] - mn0);
      float p01 = __expf(sc[nf][1] - mn0);
      float p10 = __expf(sc[nf][2] - mn1);
      float p11 = __expf(sc[nf][3] - mn1);
      rs0 += p00 + p01;
      rs1 += p10 + p11;
      ph[nf][0] = pack_h2(p00, p01);
      ph[nf][1] = pack_h2(p10, p11);
    }
    rs0 += __shfl_xor_sync(0xffffffffu, rs0, 1);
    rs0 += __shfl_xor_sync(0xffffffffu, rs0, 2);
    rs1 += __shfl_xor_sync(0xffffffffu, rs1, 1);
    rs1 += __shfl_xor_sync(0xffffffffu, rs1, 2);
    l0 = l0 * cr0 + rs0;
    l1 = l1 * cr1 + rs1;
#pragma unroll
    for (int nf = 0; nf < 16; nf++) {
      o[nf][0] *= cr0; o[nf][1] *= cr0;
      o[nf][2] *= cr1; o[nf][3] *= cr1;
    }

#pragma unroll
    for (int j = 0; j < 4; j++) {
      unsigned pa0 = ph[2 * j][0], pa1 = ph[2 * j][1];
      unsigned pa2 = ph[2 * j + 1][0], pa3 = ph[2 * j + 1][1];
      const unsigned vbase =
          smem_u32(Vs) + 2 * ((unsigned)(16 * j * FV_S) + ldm_off);
#pragma unroll
      for (int nfp = 0; nfp < 8; nfp++) {
        unsigned v0, v1, v2, v3;
        LDMATRIX_X4_TRANS(v0, v1, v2, v3, vbase + 2 * (16 * nfp));
        mma_f16(o[2 * nfp][0], o[2 * nfp][1], o[2 * nfp][2], o[2 * nfp][3],
                pa0, pa1, pa2, pa3, v0, v1);
        mma_f16(o[2 * nfp + 1][0], o[2 * nfp + 1][1], o[2 * nfp + 1][2],
                o[2 * nfp + 1][3], pa0, pa1, pa2, pa3, v2, v3);
      }
    }
  }

  const int b = bh >> 4, h = bh & 15;
  const float inv0 = 1.f / l0, inv1 = 1.f / l1;
  const int r0g = q0 + wm + lr, r1g = r0g + 8;
  __half* base0 = g_ctxh + (size_t)(b * SEQ + r0g) * DM + h * DH;
  __half* base1 = g_ctxh + (size_t)(b * SEQ + r1g) * DM + h * DH;
#pragma unroll
  for (int nf = 0; nf < 16; nf++) {
    *(__half2*)(base0 + nf * 8 + 2 * lc) =
        __floats2half2_rn(o[nf][0] * inv0, o[nf][1] * inv0);
    *(__half2*)(base1 + nf * 8 + 2 * lc) =
        __floats2half2_rn(o[nf][2] * inv1, o[nf][3] * inv1);
  }
}

// ---------------------------------------------------------------------------
extern "C" void kernel_launch(void* const* d_in, const int* in_sizes, int n_in,
                              void* d_out, int out_size) {
  const float* x    = (const float*)d_in[0];
  const float* Wqkv = (const float*)d_in[1];
  const float* bqkv = (const float*)d_in[2];
  const float* Wout = (const float*)d_in[3];
  const float* bout = (const float*)d_in[4];
  float* out = (float*)d_out;

  cudaFuncSetAttribute(gemm_h_kernel<3 * DM, true, false>,
                       cudaFuncAttributeMaxDynamicSharedMemorySize, GEMM_SMEM);
  cudaFuncSetAttribute(gemm_h_kernel<DM, false, true>,
                       cudaFuncAttributeMaxDynamicSharedMemorySize, GEMM_SMEM);
  cudaFuncSetAttribute(flash_h_kernel,
                       cudaFuncAttributeMaxDynamicSharedMemorySize, FLASH_SMEM);

  // prepass: x -> fp16; weights -> transposed [N][K] fp16
  x_to_h_kernel<<<2048, 256>>>((const float4*)x, MTOK * DM / 4);
  transpose_h_kernel<3 * DM, 1>
      <<<dim3(3 * DM / 32, DM / 32), dim3(32, 8)>>>(Wqkv);
  transpose_h_kernel<DM, 2>
      <<<dim3(DM / 32, DM / 32), dim3(32, 8)>>>(Wout);

  // QKV: CTA 128x256 -> grid (6144/256, 4096/128)
  gemm_h_kernel<3 * DM, true, false>
      <<<dim3(24, 32), 256, GEMM_SMEM>>>(bqkv, nullptr);
  flash_h_kernel<<<dim3(16, 32), 256, FLASH_SMEM>>>();
  gemm_h_kernel<DM, false, true>
      <<<dim3(8, 32), 256, GEMM_SMEM>>>(bout, out);
}

// round 15
// speedup vs baseline: 1.6077x; 1.6077x over previous
#include <cuda_runtime.h>
#include <cuda_fp16.h>
#include <cstdint>
#include <math.h>

#define NB 2
#define NH 16
#define SEQ 2048
#define DH 128
#define DM 2048          // NH*DH
#define MTOK (NB*SEQ)    // 4096

// Scratch (static device allocations — allowed; no cudaMalloc anywhere)
__device__ __half g_qkv[(size_t)3 * NB * NH * SEQ * DH];  // [3][B][H][S][D] fp16
__device__ __half g_xh[(size_t)MTOK * DM];      // x fp16            [M][K]
__device__ __half g_wqkvh[(size_t)3 * DM * DM]; // W_qkv^T fp16      [N=6144][K]
__device__ __half g_wouth[(size_t)DM * DM];     // W_out^T fp16      [N=2048][K]
__device__ __half g_ctxh[(size_t)MTOK * DM];    // ctx fp16          [M][K]

// ---------------------------------------------------------------------------
// helpers
// ---------------------------------------------------------------------------
__device__ __forceinline__ void mma_f16(float& c0, float& c1, float& c2,
                                        float& c3, unsigned a0, unsigned a1,
                                        unsigned a2, unsigned a3, unsigned b0,
                                        unsigned b1) {
  asm volatile(
      "mma.sync.aligned.m16n8k16.row.col.f32.f16.f16.f32 "
      "{%0,%1,%2,%3},{%4,%5,%6,%7},{%8,%9},{%0,%1,%2,%3};\n"
      : "+f"(c0), "+f"(c1), "+f"(c2), "+f"(c3)
      : "r"(a0), "r"(a1), "r"(a2), "r"(a3), "r"(b0), "r"(b1));
}
__device__ __forceinline__ unsigned smem_u32(const void* p) {
  return (unsigned)__cvta_generic_to_shared(p);
}
#define CP16(dst_u32, gptr) \
  asm volatile("cp.async.cg.shared.global [%0], [%1], 16;\n" ::"r"(dst_u32), \
               "l"(gptr))
#define LDMATRIX_X4(v0, v1, v2, v3, addr)                               \
  asm volatile(                                                         \
      "ldmatrix.sync.aligned.m8n8.x4.shared.b16 {%0,%1,%2,%3}, [%4];"   \
      : "=r"(v0), "=r"(v1), "=r"(v2), "=r"(v3)                          \
      : "r"(addr))
#define LDMATRIX_X4_TRANS(v0, v1, v2, v3, addr)                        \
  asm volatile(                                                        \
      "ldmatrix.sync.aligned.m8n8.x4.trans.shared.b16 {%0,%1,%2,%3}, " \
      "[%4];"                                                          \
      : "=r"(v0), "=r"(v1), "=r"(v2), "=r"(v3)                         \
      : "r"(addr))

__device__ __forceinline__ unsigned pack_h2(float a, float b) {
  __half2 h = __floats2half2_rn(a, b);
  return *(unsigned*)&h;
}

// ---------------------------------------------------------------------------
// Prepass 1: x (fp32) -> g_xh (fp16), layout unchanged
// ---------------------------------------------------------------------------
__global__ void x_to_h_kernel(const float4* __restrict__ src, int n4) {
  __half2* dst = (__half2*)g_xh;
  for (int i = blockIdx.x * blockDim.x + threadIdx.x; i < n4;
       i += gridDim.x * blockDim.x) {
    float4 v = src[i];
    dst[2 * i] = __floats2half2_rn(v.x, v.y);
    dst[2 * i + 1] = __floats2half2_rn(v.z, v.w);
  }
}

// ---------------------------------------------------------------------------
// Prepass 2: W [K=2048][NCOLS] fp32 -> W^T [NCOLS][2048] fp16
// ---------------------------------------------------------------------------
template <int NCOLS, int WHICH>
__global__ void transpose_h_kernel(const float* __restrict__ src) {
  __half* dst = (WHICH == 1) ? g_wqkvh : g_wouth;
  __shared__ float tile[32][33];
  const int n0 = blockIdx.x * 32, k0 = blockIdx.y * 32;
  const int tx = threadIdx.x, ty = threadIdx.y;  // 32 x 8
#pragma unroll
  for (int i = 0; i < 32; i += 8)
    tile[ty + i][tx] = src[(size_t)(k0 + ty + i) * NCOLS + n0 + tx];
  __syncthreads();
#pragma unroll
  for (int i = 0; i < 32; i += 8)
    dst[(size_t)(n0 + ty + i) * DM + k0 + tx] =
        __float2half_rn(tile[tx][ty + i]);
}

// ---------------------------------------------------------------------------
// FP16 tensor-core GEMM (R13 shape + ldmatrix fragments).
// CTA 128x128, K-tile 64, 8 warps (2m x 4n), warp tile 64x32, mma m16n8k16.
// Per warp per k16-step: 4 A-ldmatrix.x4 + 2 B-ldmatrix.x4 + 16 HMMA
// (was 24 LDS.32). Row stride 72 halves (36 words ≡ 4 mod 32): each 8x16B
// matrix fetch covers all 32 banks once -> conflict-free.
// Double-buffered cp.async; 73728 B smem; 2 CTAs/SM.
// ---------------------------------------------------------------------------
#define SH 72                    // halves per smem row
#define TILE_H (128 * SH)        // halves per tile (A or B)
#define GEMM_SMEM (2 * 2 * TILE_H * 2)  // 73728 B

template <int N, bool QKV_SCATTER, bool A_FROM_CTX>
__global__ __launch_bounds__(256, 2) void gemm_h_kernel(
    const float* __restrict__ bias, float* __restrict__ Cout) {
  extern __shared__ __half smh[];
  const __half* A = A_FROM_CTX ? g_ctxh : g_xh;
  const __half* Bw = QKV_SCATTER ? g_wqkvh : g_wouth;
  __half* AsBase = smh;                 // [2][128][72]
  __half* BsBase = smh + 2 * TILE_H;    // [2][128][72]
  const int K = DM;
  const int bm = blockIdx.y * 128, bn = blockIdx.x * 128;
  const int tid = threadIdx.x;
  const int warp = tid >> 5, lane = tid & 31;
  const int wm = (warp & 1) * 64;   // warp m offset
  const int wn = (warp >> 1) * 32;  // warp n offset

  float acc[4][4][4];
#pragma unroll
  for (int mf = 0; mf < 4; mf++)
#pragma unroll
    for (int nf = 0; nf < 4; nf++)
#pragma unroll
      for (int i = 0; i < 4; i++) acc[mf][nf][i] = 0.f;

  auto load_tile = [&](int k0, int buf) {
    __half* as = AsBase + buf * TILE_H;
    __half* bs = BsBase + buf * TILE_H;
#pragma unroll
    for (int i = 0; i < 4; i++) {
      int cid = tid + i * 256;
      int row = cid >> 3, u = cid & 7;
      CP16(smem_u32(as + row * SH + u * 8),
           A + (size_t)(bm + row) * K + k0 + u * 8);
    }
#pragma unroll
    for (int i = 0; i < 4; i++) {
      int cid = tid + i * 256;
      int row = cid >> 3, u = cid & 7;
      CP16(smem_u32(bs + row * SH + u * 8),
           Bw + (size_t)(bn + row) * K + k0 + u * 8);
    }
    asm volatile("cp.async.commit_group;\n");
  };

  load_tile(0, 0);

  const int lr = lane >> 2, lc = lane & 3;
  // ldmatrix lane addressing: lanes 0-15 -> rows, lanes 16-31 -> k+8
  const int lrow = lane & 15, lkh = (lane >> 4) * 8;

  for (int t = 0; t < K / 64; t++) {
    if (t + 1 < K / 64) {
      load_tile((t + 1) * 64, (t + 1) & 1);
      asm volatile("cp.async.wait_group 1;\n");
    } else {
      asm volatile("cp.async.wait_group 0;\n");
    }
    __syncthreads();

    const __half* as = AsBase + (t & 1) * TILE_H;
    const __half* bs = BsBase + (t & 1) * TILE_H;

#pragma unroll
    for (int ks = 0; ks < 4; ks++) {
      const int kh = ks * 16;
      // A frags: 4 ldmatrix.x4 (mapping verified in R14)
      unsigned a[4][4];
#pragma unroll
      for (int mf = 0; mf < 4; mf++) {
        unsigned addr = smem_u32(as + (wm + mf * 16 + lrow) * SH + kh + lkh);
        LDMATRIX_X4(a[mf][0], a[mf][1], a[mf][2], a[mf][3], addr);
      }
      // B frags: 2 ldmatrix.x4; pair p covers n-groups 2p (r0,r2), 2p+1 (r1,r3)
      unsigned b[2][4];
#pragma unroll
      for (int p = 0; p < 2; p++) {
        unsigned addr = smem_u32(bs + (wn + p * 16 + lrow) * SH + kh + lkh);
        LDMATRIX_X4(b[p][0], b[p][1], b[p][2], b[p][3], addr);
      }
#pragma unroll
      for (int mf = 0; mf < 4; mf++)
#pragma unroll
        for (int p = 0; p < 2; p++) {
          mma_f16(acc[mf][2 * p][0], acc[mf][2 * p][1], acc[mf][2 * p][2],
                  acc[mf][2 * p][3], a[mf][0], a[mf][1], a[mf][2], a[mf][3],
                  b[p][0], b[p][2]);
          mma_f16(acc[mf][2 * p + 1][0], acc[mf][2 * p + 1][1],
                  acc[mf][2 * p + 1][2], acc[mf][2 * p + 1][3], a[mf][0],
                  a[mf][1], a[mf][2], a[mf][3], b[p][1], b[p][3]);
        }
    }
    __syncthreads();
  }

  // Epilogue
#pragma unroll
  for (int mf = 0; mf < 4; mf++) {
#pragma unroll
    for (int nf = 0; nf < 4; nf++) {
      int r0 = bm + wm + mf * 16 + lr;
      int c0 = bn + wn + nf * 8 + 2 * lc;
      float bia0 = bias[c0], bia1 = bias[c0 + 1];
      float v00 = acc[mf][nf][0] + bia0, v01 = acc[mf][nf][1] + bia1;
      float v10 = acc[mf][nf][2] + bia0, v11 = acc[mf][nf][3] + bia1;
      if (QKV_SCATTER) {
        int which = c0 >> 11, rr = c0 & 2047;
        int h = rr >> 7, d = rr & 127;
#pragma unroll
        for (int rv = 0; rv < 2; rv++) {
          int m = r0 + rv * 8;
          int b = m >> 11, sidx = m & 2047;
          __half* dst = g_qkv +
                        (size_t)(((which * NB + b) * NH + h) * SEQ + sidx) *
                            DH +
                        d;
          *(__half2*)dst = rv ? __floats2half2_rn(v10, v11)
                              : __floats2half2_rn(v00, v01);
        }
      } else {
        *(float2*)(Cout + (size_t)r0 * N + c0) = make_float2(v00, v01);
        *(float2*)(Cout + (size_t)(r0 + 8) * N + c0) = make_float2(v10, v11);
      }
    }
  }
}

// ---------------------------------------------------------------------------
// FP16 flash attention (unchanged from R13 — passing).
// ---------------------------------------------------------------------------
#define FQ_S 136
#define FK_S 136
#define FV_S 136
#define FLASH_SMEM ((128 * FQ_S + 64 * FK_S + 64 * FV_S) * 2)  // 69632 B

__global__ __launch_bounds__(256, 2) void flash_h_kernel() {
  extern __shared__ __half smh[];
  __half* Qs = smh;                    // [128][136]
  __half* Ks = Qs + 128 * FQ_S;        // [64][136]
  __half* Vs = Ks + 64 * FK_S;         // [64][136]

  const int bh = blockIdx.y;
  const int qt = gridDim.x - 1 - blockIdx.x;  // longest CTAs first
  const int q0 = qt * 128;
  const __half* Qg = g_qkv + (size_t)bh * SEQ * DH + (size_t)q0 * DH;
  const __half* Kg = g_qkv + (size_t)(32 + bh) * SEQ * DH;
  const __half* Vg = g_qkv + (size_t)(64 + bh) * SEQ * DH;
  const int tid = threadIdx.x;
  const int warp = tid >> 5, lane = tid & 31;
  const int lr = lane >> 2, lc = lane & 3;
  const int wm = warp * 16;

#pragma unroll
  for (int u = 0; u < 8; u++) {
    int cid = tid + u * 256;
    int r = cid >> 4, c = (cid & 15) * 8;
    CP16(smem_u32(Qs + r * FQ_S + c), Qg + (size_t)r * DH + c);
  }
  asm volatile("cp.async.commit_group;\n");

  const int lsel = lane >> 3, lrow8 = lane & 7;
  const unsigned ldm_off =
      (unsigned)((lrow8 + 8 * (lsel & 1)) * FV_S + 8 * (lsel >> 1));

  float o[16][4];
#pragma unroll
  for (int nf = 0; nf < 16; nf++)
#pragma unroll
    for (int i = 0; i < 4; i++) o[nf][i] = 0.f;
  float m0 = -1e30f, m1 = -1e30f, l0 = 0.f, l1 = 0.f;

  const float scale = 0.08838834764831845f;  // 1/sqrt(128)
  const int nkt = 2 * qt + 2;

  for (int kt = 0; kt < nkt; kt++) {
    const int k0 = kt * 64;
    __syncthreads();
#pragma unroll
    for (int u = 0; u < 4; u++) {
      int cid = tid + u * 256;
      int r = cid >> 4, c = (cid & 15) * 8;
      CP16(smem_u32(Ks + r * FK_S + c), Kg + (size_t)(k0 + r) * DH + c);
      CP16(smem_u32(Vs + r * FV_S + c), Vg + (size_t)(k0 + r) * DH + c);
    }
    asm volatile("cp.async.commit_group;\ncp.async.wait_group 0;\n");
    __syncthreads();

    float sc[8][4];
#pragma unroll
    for (int nf = 0; nf < 8; nf++)
#pragma unroll
      for (int i = 0; i < 4; i++) sc[nf][i] = 0.f;
#pragma unroll
    for (int ks = 0; ks < 8; ks++) {
      const int kh = ks * 16;
      const __half* ap = Qs + (wm + lr) * FQ_S + kh + 2 * lc;
      unsigned a0 = *(const unsigned*)(ap);
      unsigned a1 = *(const unsigned*)(ap + 8 * FQ_S);
      unsigned a2 = *(const unsigned*)(ap + 8);
      unsigned a3 = *(const unsigned*)(ap + 8 * FQ_S + 8);
#pragma unroll
      for (int nf = 0; nf < 8; nf++) {
        const __half* bp = Ks + (nf * 8 + lr) * FK_S + kh + 2 * lc;
        unsigned b0 = *(const unsigned*)(bp);
        unsigned b1 = *(const unsigned*)(bp + 8);
        mma_f16(sc[nf][0], sc[nf][1], sc[nf][2], sc[nf][3], a0, a1, a2, a3,
                b0, b1);
      }
    }
#pragma unroll
    for (int nf = 0; nf < 8; nf++)
#pragma unroll
      for (int i = 0; i < 4; i++) sc[nf][i] *= scale;

    const int r0g = q0 + wm + lr, r1g = r0g + 8;
    if (k0 + 63 > r0g) {
#pragma unroll
      for (int nf = 0; nf < 8; nf++) {
        int cg = k0 + nf * 8 + 2 * lc;
        if (cg > r0g) sc[nf][0] = -1e30f;
        if (cg + 1 > r0g) sc[nf][1] = -1e30f;
        if (cg > r1g) sc[nf][2] = -1e30f;
        if (cg + 1 > r1g) sc[nf][3] = -1e30f;
      }
    }

    float mx0 = sc[0][0], mx1 = sc[0][2];
#pragma unroll
    for (int nf = 0; nf < 8; nf++) {
      mx0 = fmaxf(mx0, fmaxf(sc[nf][0], sc[nf][1]));
      mx1 = fmaxf(mx1, fmaxf(sc[nf][2], sc[nf][3]));
    }
    mx0 = fmaxf(mx0, __shfl_xor_sync(0xffffffffu, mx0, 1));
    mx0 = fmaxf(mx0, __shfl_xor_sync(0xffffffffu, mx0, 2));
    mx1 = fmaxf(mx1, __shfl_xor_sync(0xffffffffu, mx1, 1));
    mx1 = fmaxf(mx1, __shfl_xor_sync(0xffffffffu, mx1, 2));
    float mn0 = fmaxf(m0, mx0), mn1 = fmaxf(m1, mx1);
    float cr0 = __expf(m0 - mn0), cr1 = __expf(m1 - mn1);
    m0 = mn0; m1 = mn1;
    float rs0 = 0.f, rs1 = 0.f;
    unsigned ph[8][2];
#pragma unroll
    for (int nf = 0; nf < 8; nf++) {
      float p00 = __expf(sc[nf][0] - mn0);
      float p01 = __expf(sc[nf][1] - mn0);
      float p10 = __expf(sc[nf][2] - mn1);
      float p11 = __expf(sc[nf][3] - mn1);
      rs0 += p00 + p01;
      rs1 += p10 + p11;
      ph[nf][0] = pack_h2(p00, p01);
      ph[nf][1] = pack_h2(p10, p11);
    }
    rs0 += __shfl_xor_sync(0xffffffffu, rs0, 1);
    rs0 += __shfl_xor_sync(0xffffffffu, rs0, 2);
    rs1 += __shfl_xor_sync(0xffffffffu, rs1, 1);
    rs1 += __shfl_xor_sync(0xffffffffu, rs1, 2);
    l0 = l0 * cr0 + rs0;
    l1 = l1 * cr1 + rs1;
#pragma unroll
    for (int nf = 0; nf < 16; nf++) {
      o[nf][0] *= cr0; o[nf][1] *= cr0;
      o[nf][2] *= cr1; o[nf][3] *= cr1;
    }

#pragma unroll
    for (int j = 0; j < 4; j++) {
      unsigned pa0 = ph[2 * j][0], pa1 = ph[2 * j][1];
      unsigned pa2 = ph[2 * j + 1][0], pa3 = ph[2 * j + 1][1];
      const unsigned vbase =
          smem_u32(Vs) + 2 * ((unsigned)(16 * j * FV_S) + ldm_off);
#pragma unroll
      for (int nfp = 0; nfp < 8; nfp++) {
        unsigned v0, v1, v2, v3;
        LDMATRIX_X4_TRANS(v0, v1, v2, v3, vbase + 2 * (16 * nfp));
        mma_f16(o[2 * nfp][0], o[2 * nfp][1], o[2 * nfp][2], o[2 * nfp][3],
                pa0, pa1, pa2, pa3, v0, v1);
        mma_f16(o[2 * nfp + 1][0], o[2 * nfp + 1][1], o[2 * nfp + 1][2],
                o[2 * nfp + 1][3], pa0, pa1, pa2, pa3, v2, v3);
      }
    }
  }

  const int b = bh >> 4, h = bh & 15;
  const float inv0 = 1.f / l0, inv1 = 1.f / l1;
  const int r0g = q0 + wm + lr, r1g = r0g + 8;
  __half* base0 = g_ctxh + (size_t)(b * SEQ + r0g) * DM + h * DH;
  __half* base1 = g_ctxh + (size_t)(b * SEQ + r1g) * DM + h * DH;
#pragma unroll
  for (int nf = 0; nf < 16; nf++) {
    *(__half2*)(base0 + nf * 8 + 2 * lc) =
        __floats2half2_rn(o[nf][0] * inv0, o[nf][1] * inv0);
    *(__half2*)(base1 + nf * 8 + 2 * lc) =
        __floats2half2_rn(o[nf][2] * inv1, o[nf][3] * inv1);
  }
}

// ---------------------------------------------------------------------------
extern "C" void kernel_launch(void* const* d_in, const int* in_sizes, int n_in,
                              void* d_out, int out_size) {
  const float* x    = (const float*)d_in[0];
  const float* Wqkv = (const float*)d_in[1];
  const float* bqkv = (const float*)d_in[2];
  const float* Wout = (const float*)d_in[3];
  const float* bout = (const float*)d_in[4];
  float* out = (float*)d_out;

  cudaFuncSetAttribute(gemm_h_kernel<3 * DM, true, false>,
                       cudaFuncAttributeMaxDynamicSharedMemorySize, GEMM_SMEM);
  cudaFuncSetAttribute(gemm_h_kernel<DM, false, true>,
                       cudaFuncAttributeMaxDynamicSharedMemorySize, GEMM_SMEM);
  cudaFuncSetAttribute(flash_h_kernel,
                       cudaFuncAttributeMaxDynamicSharedMemorySize, FLASH_SMEM);

  // prepass: x -> fp16; weights -> transposed [N][K] fp16
  x_to_h_kernel<<<2048, 256>>>((const float4*)x, MTOK * DM / 4);
  transpose_h_kernel<3 * DM, 1>
      <<<dim3(3 * DM / 32, DM / 32), dim3(32, 8)>>>(Wqkv);
  transpose_h_kernel<DM, 2>
      <<<dim3(DM / 32, DM / 32), dim3(32, 8)>>>(Wout);

  gemm_h_kernel<3 * DM, true, false>
      <<<dim3(48, 32), 256, GEMM_SMEM>>>(bqkv, nullptr);
  flash_h_kernel<<<dim3(16, 32), 256, FLASH_SMEM>>>();
  gemm_h_kernel<DM, false, true>
      <<<dim3(16, 32), 256, GEMM_SMEM>>>(bout, out);
}

// round 16
// speedup vs baseline: 1.6523x; 1.0278x over previous
#include <cuda_runtime.h>
#include <cuda_fp16.h>
#include <cstdint>
#include <math.h>

#define NB 2
#define NH 16
#define SEQ 2048
#define DH 128
#define DM 2048          // NH*DH
#define MTOK (NB*SEQ)    // 4096

// Scratch (static device allocations — allowed; no cudaMalloc anywhere)
__device__ __half g_qkv[(size_t)3 * NB * NH * SEQ * DH];  // [3][B][H][S][D] fp16
__device__ __half g_xh[(size_t)MTOK * DM];      // x fp16            [M][K]
__device__ __half g_wqkvh[(size_t)3 * DM * DM]; // W_qkv^T fp16      [N=6144][K]
__device__ __half g_wouth[(size_t)DM * DM];     // W_out^T fp16      [N=2048][K]
__device__ __half g_ctxh[(size_t)MTOK * DM];    // ctx fp16          [M][K]

// ---------------------------------------------------------------------------
// helpers
// ---------------------------------------------------------------------------
__device__ __forceinline__ void mma_f16(float& c0, float& c1, float& c2,
                                        float& c3, unsigned a0, unsigned a1,
                                        unsigned a2, unsigned a3, unsigned b0,
                                        unsigned b1) {
  asm volatile(
      "mma.sync.aligned.m16n8k16.row.col.f32.f16.f16.f32 "
      "{%0,%1,%2,%3},{%4,%5,%6,%7},{%8,%9},{%0,%1,%2,%3};\n"
      : "+f"(c0), "+f"(c1), "+f"(c2), "+f"(c3)
      : "r"(a0), "r"(a1), "r"(a2), "r"(a3), "r"(b0), "r"(b1));
}
__device__ __forceinline__ unsigned smem_u32(const void* p) {
  return (unsigned)__cvta_generic_to_shared(p);
}
#define CP16(dst_u32, gptr) \
  asm volatile("cp.async.cg.shared.global [%0], [%1], 16;\n" ::"r"(dst_u32), \
               "l"(gptr))
#define LDMATRIX_X4_TRANS(v0, v1, v2, v3, addr)                        \
  asm volatile(                                                        \
      "ldmatrix.sync.aligned.m8n8.x4.trans.shared.b16 {%0,%1,%2,%3}, " \
      "[%4];"                                                          \
      : "=r"(v0), "=r"(v1), "=r"(v2), "=r"(v3)                         \
      : "r"(addr))

__device__ __forceinline__ unsigned pack_h2(float a, float b) {
  __half2 h = __floats2half2_rn(a, b);
  return *(unsigned*)&h;
}

// ---------------------------------------------------------------------------
// Prepass 1: x (fp32) -> g_xh (fp16), layout unchanged
// ---------------------------------------------------------------------------
__global__ void x_to_h_kernel(const float4* __restrict__ src, int n4) {
  __half2* dst = (__half2*)g_xh;
  for (int i = blockIdx.x * blockDim.x + threadIdx.x; i < n4;
       i += gridDim.x * blockDim.x) {
    float4 v = src[i];
    dst[2 * i] = __floats2half2_rn(v.x, v.y);
    dst[2 * i + 1] = __floats2half2_rn(v.z, v.w);
  }
}

// ---------------------------------------------------------------------------
// Prepass 2: W [K=2048][NCOLS] fp32 -> W^T [NCOLS][2048] fp16
// ---------------------------------------------------------------------------
template <int NCOLS, int WHICH>
__global__ void transpose_h_kernel(const float* __restrict__ src) {
  __half* dst = (WHICH == 1) ? g_wqkvh : g_wouth;
  __shared__ float tile[32][33];
  const int n0 = blockIdx.x * 32, k0 = blockIdx.y * 32;
  const int tx = threadIdx.x, ty = threadIdx.y;  // 32 x 8
#pragma unroll
  for (int i = 0; i < 32; i += 8)
    tile[ty + i][tx] = src[(size_t)(k0 + ty + i) * NCOLS + n0 + tx];
  __syncthreads();
#pragma unroll
  for (int i = 0; i < 32; i += 8)
    dst[(size_t)(n0 + ty + i) * DM + k0 + tx] =
        __float2half_rn(tile[tx][ty + i]);
}

// ---------------------------------------------------------------------------
// FP16 tensor-core GEMM (R13 mainloop, 3-stage cp.async pipeline).
// CTA 128x128, K-tile 64, 8 warps (2m x 4n), warp tile 64x32, mma m16n8k16.
// 3 stages: loads run 2 tiles ahead; ONE __syncthreads per iteration.
// Row stride 72 halves (36 words ≡ 4 mod 32): conflict-free frag loads.
// Smem 110592 B; 2 CTAs/SM (221 KB <= 228 KB).
// ---------------------------------------------------------------------------
#define SH 72                    // halves per smem row
#define TILE_H (128 * SH)        // halves per tile (A or B)
#define NSTG 3
#define GEMM_SMEM (NSTG * 2 * TILE_H * 2)  // 110592 B

template <int N, bool QKV_SCATTER, bool A_FROM_CTX>
__global__ __launch_bounds__(256, 2) void gemm_h_kernel(
    const float* __restrict__ bias, float* __restrict__ Cout) {
  extern __shared__ __half smh[];
  const __half* A = A_FROM_CTX ? g_ctxh : g_xh;
  const __half* Bw = QKV_SCATTER ? g_wqkvh : g_wouth;
  __half* AsBase = smh;                    // [3][128][72]
  __half* BsBase = smh + NSTG * TILE_H;    // [3][128][72]
  const int K = DM;
  const int KT2 = K / 64;  // 32
  const int bm = blockIdx.y * 128, bn = blockIdx.x * 128;
  const int tid = threadIdx.x;
  const int warp = tid >> 5, lane = tid & 31;
  const int wm = (warp & 1) * 64;   // warp m offset
  const int wn = (warp >> 1) * 32;  // warp n offset

  float acc[4][4][4];
#pragma unroll
  for (int mf = 0; mf < 4; mf++)
#pragma unroll
    for (int nf = 0; nf < 4; nf++)
#pragma unroll
      for (int i = 0; i < 4; i++) acc[mf][nf][i] = 0.f;

  auto load_tile = [&](int k0, int buf) {
    __half* as = AsBase + buf * TILE_H;
    __half* bs = BsBase + buf * TILE_H;
#pragma unroll
    for (int i = 0; i < 4; i++) {
      int cid = tid + i * 256;
      int row = cid >> 3, u = cid & 7;
      CP16(smem_u32(as + row * SH + u * 8),
           A + (size_t)(bm + row) * K + k0 + u * 8);
    }
#pragma unroll
    for (int i = 0; i < 4; i++) {
      int cid = tid + i * 256;
      int row = cid >> 3, u = cid & 7;
      CP16(smem_u32(bs + row * SH + u * 8),
           Bw + (size_t)(bn + row) * K + k0 + u * 8);
    }
    asm volatile("cp.async.commit_group;\n");
  };

  load_tile(0, 0);
  load_tile(64, 1);

  const int lr = lane >> 2, lc = lane & 3;

  for (int t = 0; t < KT2; t++) {
    // tile t complete (t+1 may still be in flight)
    if (t + 1 < KT2)
      asm volatile("cp.async.wait_group 1;\n");
    else
      asm volatile("cp.async.wait_group 0;\n");
    __syncthreads();  // also guarantees all warps done computing tile t-1
    if (t + 2 < KT2) load_tile((t + 2) * 64, (t + 2) % NSTG);

    const __half* as = AsBase + (t % NSTG) * TILE_H;
    const __half* bs = BsBase + (t % NSTG) * TILE_H;

#pragma unroll
    for (int ks = 0; ks < 4; ks++) {
      const int kh = ks * 16;
      unsigned a[4][4];
#pragma unroll
      for (int mf = 0; mf < 4; mf++) {
        const __half* ap = as + (wm + mf * 16 + lr) * SH + kh + 2 * lc;
        a[mf][0] = *(const unsigned*)(ap);
        a[mf][1] = *(const unsigned*)(ap + 8 * SH);
        a[mf][2] = *(const unsigned*)(ap + 8);
        a[mf][3] = *(const unsigned*)(ap + 8 * SH + 8);
      }
      unsigned b[4][2];
#pragma unroll
      for (int nf = 0; nf < 4; nf++) {
        const __half* bp = bs + (wn + nf * 8 + lr) * SH + kh + 2 * lc;
        b[nf][0] = *(const unsigned*)(bp);
        b[nf][1] = *(const unsigned*)(bp + 8);
      }
#pragma unroll
      for (int mf = 0; mf < 4; mf++)
#pragma unroll
        for (int nf = 0; nf < 4; nf++)
          mma_f16(acc[mf][nf][0], acc[mf][nf][1], acc[mf][nf][2],
                  acc[mf][nf][3], a[mf][0], a[mf][1], a[mf][2], a[mf][3],
                  b[nf][0], b[nf][1]);
    }
  }

  // Epilogue
#pragma unroll
  for (int mf = 0; mf < 4; mf++) {
#pragma unroll
    for (int nf = 0; nf < 4; nf++) {
      int r0 = bm + wm + mf * 16 + lr;
      int c0 = bn + wn + nf * 8 + 2 * lc;
      float bia0 = bias[c0], bia1 = bias[c0 + 1];
      float v00 = acc[mf][nf][0] + bia0, v01 = acc[mf][nf][1] + bia1;
      float v10 = acc[mf][nf][2] + bia0, v11 = acc[mf][nf][3] + bia1;
      if (QKV_SCATTER) {
        int which = c0 >> 11, rr = c0 & 2047;
        int h = rr >> 7, d = rr & 127;
#pragma unroll
        for (int rv = 0; rv < 2; rv++) {
          int m = r0 + rv * 8;
          int b = m >> 11, sidx = m & 2047;
          __half* dst = g_qkv +
                        (size_t)(((which * NB + b) * NH + h) * SEQ + sidx) *
                            DH +
                        d;
          *(__half2*)dst = rv ? __floats2half2_rn(v10, v11)
                              : __floats2half2_rn(v00, v01);
        }
      } else {
        *(float2*)(Cout + (size_t)r0 * N + c0) = make_float2(v00, v01);
        *(float2*)(Cout + (size_t)(r0 + 8) * N + c0) = make_float2(v10, v11);
      }
    }
  }
}

// ---------------------------------------------------------------------------
// FP16 flash attention (unchanged from R13 — passing).
// ---------------------------------------------------------------------------
#define FQ_S 136
#define FK_S 136
#define FV_S 136
#define FLASH_SMEM ((128 * FQ_S + 64 * FK_S + 64 * FV_S) * 2)  // 69632 B

__global__ __launch_bounds__(256, 2) void flash_h_kernel() {
  extern __shared__ __half smh[];
  __half* Qs = smh;                    // [128][136]
  __half* Ks = Qs + 128 * FQ_S;        // [64][136]
  __half* Vs = Ks + 64 * FK_S;         // [64][136]

  const int bh = blockIdx.y;
  const int qt = gridDim.x - 1 - blockIdx.x;  // longest CTAs first
  const int q0 = qt * 128;
  const __half* Qg = g_qkv + (size_t)bh * SEQ * DH + (size_t)q0 * DH;
  const __half* Kg = g_qkv + (size_t)(32 + bh) * SEQ * DH;
  const __half* Vg = g_qkv + (size_t)(64 + bh) * SEQ * DH;
  const int tid = threadIdx.x;
  const int warp = tid >> 5, lane = tid & 31;
  const int lr = lane >> 2, lc = lane & 3;
  const int wm = warp * 16;

#pragma unroll
  for (int u = 0; u < 8; u++) {
    int cid = tid + u * 256;
    int r = cid >> 4, c = (cid & 15) * 8;
    CP16(smem_u32(Qs + r * FQ_S + c), Qg + (size_t)r * DH + c);
  }
  asm volatile("cp.async.commit_group;\n");

  const int lsel = lane >> 3, lrow8 = lane & 7;
  const unsigned ldm_off =
      (unsigned)((lrow8 + 8 * (lsel & 1)) * FV_S + 8 * (lsel >> 1));

  float o[16][4];
#pragma unroll
  for (int nf = 0; nf < 16; nf++)
#pragma unroll
    for (int i = 0; i < 4; i++) o[nf][i] = 0.f;
  float m0 = -1e30f, m1 = -1e30f, l0 = 0.f, l1 = 0.f;

  const float scale = 0.08838834764831845f;  // 1/sqrt(128)
  const int nkt = 2 * qt + 2;

  for (int kt = 0; kt < nkt; kt++) {
    const int k0 = kt * 64;
    __syncthreads();
#pragma unroll
    for (int u = 0; u < 4; u++) {
      int cid = tid + u * 256;
      int r = cid >> 4, c = (cid & 15) * 8;
      CP16(smem_u32(Ks + r * FK_S + c), Kg + (size_t)(k0 + r) * DH + c);
      CP16(smem_u32(Vs + r * FV_S + c), Vg + (size_t)(k0 + r) * DH + c);
    }
    asm volatile("cp.async.commit_group;\ncp.async.wait_group 0;\n");
    __syncthreads();

    float sc[8][4];
#pragma unroll
    for (int nf = 0; nf < 8; nf++)
#pragma unroll
      for (int i = 0; i < 4; i++) sc[nf][i] = 0.f;
#pragma unroll
    for (int ks = 0; ks < 8; ks++) {
      const int kh = ks * 16;
      const __half* ap = Qs + (wm + lr) * FQ_S + kh + 2 * lc;
      unsigned a0 = *(const unsigned*)(ap);
      unsigned a1 = *(const unsigned*)(ap + 8 * FQ_S);
      unsigned a2 = *(const unsigned*)(ap + 8);
      unsigned a3 = *(const unsigned*)(ap + 8 * FQ_S + 8);
#pragma unroll
      for (int nf = 0; nf < 8; nf++) {
        const __half* bp = Ks + (nf * 8 + lr) * FK_S + kh + 2 * lc;
        unsigned b0 = *(const unsigned*)(bp);
        unsigned b1 = *(const unsigned*)(bp + 8);
        mma_f16(sc[nf][0], sc[nf][1], sc[nf][2], sc[nf][3], a0, a1, a2, a3,
                b0, b1);
      }
    }
#pragma unroll
    for (int nf = 0; nf < 8; nf++)
#pragma unroll
      for (int i = 0; i < 4; i++) sc[nf][i] *= scale;

    const int r0g = q0 + wm + lr, r1g = r0g + 8;
    if (k0 + 63 > r0g) {
#pragma unroll
      for (int nf = 0; nf < 8; nf++) {
        int cg = k0 + nf * 8 + 2 * lc;
        if (cg > r0g) sc[nf][0] = -1e30f;
        if (cg + 1 > r0g) sc[nf][1] = -1e30f;
        if (cg > r1g) sc[nf][2] = -1e30f;
        if (cg + 1 > r1g) sc[nf][3] = -1e30f;
      }
    }

    float mx0 = sc[0][0], mx1 = sc[0][2];
#pragma unroll
    for (int nf = 0; nf < 8; nf++) {
      mx0 = fmaxf(mx0, fmaxf(sc[nf][0], sc[nf][1]));
      mx1 = fmaxf(mx1, fmaxf(sc[nf][2], sc[nf][3]));
    }
    mx0 = fmaxf(mx0, __shfl_xor_sync(0xffffffffu, mx0, 1));
    mx0 = fmaxf(mx0, __shfl_xor_sync(0xffffffffu, mx0, 2));
    mx1 = fmaxf(mx1, __shfl_xor_sync(0xffffffffu, mx1, 1));
    mx1 = fmaxf(mx1, __shfl_xor_sync(0xffffffffu, mx1, 2));
    float mn0 = fmaxf(m0, mx0), mn1 = fmaxf(m1, mx1);
    float cr0 = __expf(m0 - mn0), cr1 = __expf(m1 - mn1);
    m0 = mn0; m1 = mn1;
    float rs0 = 0.f, rs1 = 0.f;
    unsigned ph[8][2];
#pragma unroll
    for (int nf = 0; nf < 8; nf++) {
      float p00 = __expf(sc[nf][0] - mn0);
      float p01 = __expf(sc[nf][1] - mn0);
      float p10 = __expf(sc[nf][2] - mn1);
      float p11 = __expf(sc[nf][3] - mn1);
      rs0 += p00 + p01;
      rs1 += p10 + p11;
      ph[nf][0] = pack_h2(p00, p01);
      ph[nf][1] = pack_h2(p10, p11);
    }
    rs0 += __shfl_xor_sync(0xffffffffu, rs0, 1);
    rs0 += __shfl_xor_sync(0xffffffffu, rs0, 2);
    rs1 += __shfl_xor_sync(0xffffffffu, rs1, 1);
    rs1 += __shfl_xor_sync(0xffffffffu, rs1, 2);
    l0 = l0 * cr0 + rs0;
    l1 = l1 * cr1 + rs1;
#pragma unroll
    for (int nf = 0; nf < 16; nf++) {
      o[nf][0] *= cr0; o[nf][1] *= cr0;
      o[nf][2] *= cr1; o[nf][3] *= cr1;
    }

#pragma unroll
    for (int j = 0; j < 4; j++) {
      unsigned pa0 = ph[2 * j][0], pa1 = ph[2 * j][1];
      unsigned pa2 = ph[2 * j + 1][0], pa3 = ph[2 * j + 1][1];
      const unsigned vbase =
          smem_u32(Vs) + 2 * ((unsigned)(16 * j * FV_S) + ldm_off);
#pragma unroll
      for (int nfp = 0; nfp < 8; nfp++) {
        unsigned v0, v1, v2, v3;
        LDMATRIX_X4_TRANS(v0, v1, v2, v3, vbase + 2 * (16 * nfp));
        mma_f16(o[2 * nfp][0], o[2 * nfp][1], o[2 * nfp][2], o[2 * nfp][3],
                pa0, pa1, pa2, pa3, v0, v1);
        mma_f16(o[2 * nfp + 1][0], o[2 * nfp + 1][1], o[2 * nfp + 1][2],
                o[2 * nfp + 1][3], pa0, pa1, pa2, pa3, v2, v3);
      }
    }
  }

  const int b = bh >> 4, h = bh & 15;
  const float inv0 = 1.f / l0, inv1 = 1.f / l1;
  const int r0g = q0 + wm + lr, r1g = r0g + 8;
  __half* base0 = g_ctxh + (size_t)(b * SEQ + r0g) * DM + h * DH;
  __half* base1 = g_ctxh + (size_t)(b * SEQ + r1g) * DM + h * DH;
#pragma unroll
  for (int nf = 0; nf < 16; nf++) {
    *(__half2*)(base0 + nf * 8 + 2 * lc) =
        __floats2half2_rn(o[nf][0] * inv0, o[nf][1] * inv0);
    *(__half2*)(base1 + nf * 8 + 2 * lc) =
        __floats2half2_rn(o[nf][2] * inv1, o[nf][3] * inv1);
  }
}

// ---------------------------------------------------------------------------
extern "C" void kernel_launch(void* const* d_in, const int* in_sizes, int n_in,
                              void* d_out, int out_size) {
  const float* x    = (const float*)d_in[0];
  const float* Wqkv = (const float*)d_in[1];
  const float* bqkv = (const float*)d_in[2];
  const float* Wout = (const float*)d_in[3];
  const float* bout = (const float*)d_in[4];
  float* out = (float*)d_out;

  cudaFuncSetAttribute(gemm_h_kernel<3 * DM, true, false>,
                       cudaFuncAttributeMaxDynamicSharedMemorySize, GEMM_SMEM);
  cudaFuncSetAttribute(gemm_h_kernel<DM, false, true>,
                       cudaFuncAttributeMaxDynamicSharedMemorySize, GEMM_SMEM);
  cudaFuncSetAttribute(flash_h_kernel,
                       cudaFuncAttributeMaxDynamicSharedMemorySize, FLASH_SMEM);

  // prepass: x -> fp16; weights -> transposed [N][K] fp16
  x_to_h_kernel<<<2048, 256>>>((const float4*)x, MTOK * DM / 4);
  transpose_h_kernel<3 * DM, 1>
      <<<dim3(3 * DM / 32, DM / 32), dim3(32, 8)>>>(Wqkv);
  transpose_h_kernel<DM, 2>
      <<<dim3(DM / 32, DM / 32), dim3(32, 8)>>>(Wout);

  gemm_h_kernel<3 * DM, true, false>
      <<<dim3(48, 32), 256, GEMM_SMEM>>>(bqkv, nullptr);
  flash_h_kernel<<<dim3(16, 32), 256, FLASH_SMEM>>>();
  gemm_h_kernel<DM, false, true>
      <<<dim3(16, 32), 256, GEMM_SMEM>>>(bout, out);
}